// round 1
// baseline (speedup 1.0000x reference)
#include <cuda_runtime.h>
#include <cstdint>

// Problem constants
#define B 8192
#define NNODE 64
#define DOBS 16
#define XLEN (B * NNODE * 18)            // 9437184 floats (x region)
#define EPB 630                           // edge columns per batch (10*(N-1))
#define ETOT (B * EPB)                    // 5160960 columns
#define KEY_STRIDE 640                    // padded per-batch key stride

// Scratch (static device globals — no runtime allocation)
__device__ unsigned short g_keys[(size_t)B * KEY_STRIDE];
__device__ int g_cnt[B];
__device__ int g_off[B];

// ---------------------------------------------------------------------------
// Kernel A: write x = concat(obs, init) and fill edge region with -1
// ---------------------------------------------------------------------------
__global__ void write_x_fill(const float* __restrict__ obs,
                             const float* __restrict__ ego,
                             const float* __restrict__ other,
                             float* __restrict__ out) {
    int i = blockIdx.x * blockDim.x + threadIdx.x;
    const int total = XLEN + 2 * ETOT;
    if (i >= total) return;
    if (i < XLEN) {
        int node = i / 18;
        int d = i - node * 18;
        float v;
        if (d < DOBS) {
            v = obs[(size_t)node * DOBS + d];
        } else {
            int n = node & (NNODE - 1);
            v = (n == 0) ? ego[d - DOBS] : other[d - DOBS];
        }
        out[i] = v;
    } else {
        out[i] = -1.0f;
    }
}

// ---------------------------------------------------------------------------
// Kernel B: per-batch edge construction. One block of 64 threads per batch.
// ---------------------------------------------------------------------------
__global__ void __launch_bounds__(64) build_edges(const float* __restrict__ obs) {
    int b = blockIdx.x;
    int t = threadIdx.x;            // 0..63
    int lane = t & 31, w = t >> 5;

    __shared__ float sx[64], sy[64];
    __shared__ int sord[64];
    __shared__ unsigned sbits[5][2];
    __shared__ unsigned bitmap[128];   // 4096 bits: key = u*64 + v
    __shared__ int warpsum[2];

    const float* base = obs + (size_t)b * NNODE * DOBS;
    float2 xy = *(const float2*)(base + t * DOBS);   // 64B-aligned rows
    sx[t] = xy.x;
    sy[t] = xy.y;
    bitmap[t] = 0u;
    bitmap[t + 64] = 0u;
    __syncthreads();

    // Stable rank by x (ties broken by original index)
    float xi = sx[t];
    int r = 0;
#pragma unroll
    for (int j = 0; j < 64; j++) {
        float xj = sx[j];
        r += (xj < xi) || (xj == xi && j < t);
    }
    sord[r] = t;
    __syncthreads();

    int node = sord[t];           // node at sorted position t
    float ys = sy[node];

    const float T1 = (float)(1.0 / 3.0);
    const float T2 = (float)(2.0 / 3.0);
    bool f0 = (ys <= T1) && (ys > 0.0f);
    bool f1 = (ys > T1) && (ys <= T2);
    bool f2 = (ys >= T2) && (ys < 1.0f);
    bool mm[5];
    mm[0] = f0; mm[1] = f1; mm[2] = f2; mm[3] = f0 || f1; mm[4] = f1 || f2;

#pragma unroll
    for (int m = 0; m < 5; m++) {
        unsigned bal = __ballot_sync(0xffffffffu, mm[m]);
        if (lane == 0) sbits[m][w] = bal;
    }
    __syncthreads();

#pragma unroll
    for (int m = 0; m < 5; m++) {
        if (mm[m] && t < 63) {
            unsigned long long bits =
                ((unsigned long long)sbits[m][1] << 32) | (unsigned long long)sbits[m][0];
            unsigned long long rest = bits >> (t + 1);
            if (rest) {
                int nk = t + 1 + (__ffsll((long long)rest) - 1);
                int v = sord[nk];
                int k1 = node * 64 + v;
                int k2 = v * 64 + node;
                atomicOr(&bitmap[k1 >> 5], 1u << (k1 & 31));
                atomicOr(&bitmap[k2 >> 5], 1u << (k2 & 31));
            }
        }
    }
    __syncthreads();

    // Compact: enumerate set bits in ascending key order (= lexsorted unique)
    unsigned w0 = bitmap[2 * t];
    unsigned w1 = bitmap[2 * t + 1];
    int c = __popc(w0) + __popc(w1);

    // block exclusive scan over 64 values (2 warps)
    int inc = c;
#pragma unroll
    for (int d = 1; d < 32; d <<= 1) {
        int nv = __shfl_up_sync(0xffffffffu, inc, d);
        if (lane >= d) inc += nv;
    }
    if (lane == 31) warpsum[w] = inc;
    __syncthreads();
    int excl = inc - c + (w == 1 ? warpsum[0] : 0);
    if (t == 0) g_cnt[b] = warpsum[0] + warpsum[1];

    unsigned short* kb = g_keys + (size_t)b * KEY_STRIDE;
    int pos = excl;
    int kbase = t * 64;
    while (w0) {
        int bit = __ffs(w0) - 1;
        w0 &= (w0 - 1);
        kb[pos++] = (unsigned short)(kbase + bit);
    }
    kbase += 32;
    while (w1) {
        int bit = __ffs(w1) - 1;
        w1 &= (w1 - 1);
        kb[pos++] = (unsigned short)(kbase + bit);
    }
}

// ---------------------------------------------------------------------------
// Kernel C: exclusive scan of g_cnt[8192] -> g_off. One block, 1024 threads.
// ---------------------------------------------------------------------------
__global__ void __launch_bounds__(1024) scan_counts() {
    int t = threadIdx.x;
    int lane = t & 31, wid = t >> 5;
    __shared__ int wsum[32];

    int base = t * 8;
    int v[8];
    int s = 0;
#pragma unroll
    for (int i = 0; i < 8; i++) {
        v[i] = s;
        s += g_cnt[base + i];
    }
    int inc = s;
#pragma unroll
    for (int d = 1; d < 32; d <<= 1) {
        int nv = __shfl_up_sync(0xffffffffu, inc, d);
        if (lane >= d) inc += nv;
    }
    if (lane == 31) wsum[wid] = inc;
    __syncthreads();
    if (wid == 0) {
        int wv = wsum[lane];
        int winc = wv;
#pragma unroll
        for (int d = 1; d < 32; d <<= 1) {
            int nv = __shfl_up_sync(0xffffffffu, winc, d);
            if (lane >= d) winc += nv;
        }
        wsum[lane] = winc - wv;   // exclusive warp offsets
    }
    __syncthreads();
    int excl = inc - s + wsum[wid];
#pragma unroll
    for (int i = 0; i < 8; i++) g_off[base + i] = excl + v[i];
}

// ---------------------------------------------------------------------------
// Kernel D: scatter per-batch keys to final (src,dst) float positions
// ---------------------------------------------------------------------------
__global__ void __launch_bounds__(64) scatter_edges(float* __restrict__ out) {
    int b = blockIdx.x;
    int t = threadIdx.x;
    int cnt = g_cnt[b];
    int off = g_off[b];
    const unsigned short* kb = g_keys + (size_t)b * KEY_STRIDE;
    float* src_out = out + XLEN;
    float* dst_out = out + XLEN + ETOT;
    int nb = b * NNODE;
    for (int i = t; i < cnt; i += 64) {
        int k = kb[i];
        src_out[off + i] = (float)(nb + (k >> 6));
        dst_out[off + i] = (float)(nb + (k & 63));
    }
}

// ---------------------------------------------------------------------------
extern "C" void kernel_launch(void* const* d_in, const int* in_sizes, int n_in,
                              void* d_out, int out_size) {
    const float* obs = (const float*)d_in[0];
    const float* ego = (const float*)d_in[1];
    const float* other = (const float*)d_in[2];
    float* out = (float*)d_out;

    const int total = XLEN + 2 * ETOT;
    int threads = 256;
    int blocks = (total + threads - 1) / threads;
    write_x_fill<<<blocks, threads>>>(obs, ego, other, out);
    build_edges<<<B, 64>>>(obs);
    scan_counts<<<1, 1024>>>();
    scatter_edges<<<B, 64>>>(out);
}

// round 2
// speedup vs baseline: 1.7686x; 1.7686x over previous
#include <cuda_runtime.h>
#include <cstdint>

// Problem constants
#define B 8192
#define NNODE 64
#define DOBS 16
#define XROW 18
#define XLEN (B * NNODE * XROW)          // 9437184 floats (x region)
#define EPB 630                          // max edge columns per batch
#define ETOT (B * EPB)                   // 5160960 columns
#define KEY_STRIDE 640

// Scratch (static device globals — no runtime allocation)
__device__ unsigned short g_keys[(size_t)B * KEY_STRIDE];
__device__ int g_cnt[B];
__device__ int g_off[B];
__device__ int g_total;

// ---------------------------------------------------------------------------
// Kernel 1: fused x-write + per-batch edge construction. 128 thr/block.
// ---------------------------------------------------------------------------
__global__ void __launch_bounds__(128) build_edges_x(const float* __restrict__ obs,
                                                     const float* __restrict__ ego,
                                                     const float* __restrict__ other,
                                                     float* __restrict__ out) {
    int b = blockIdx.x;
    int t = threadIdx.x;              // 0..127
    int lane = t & 31, w = t >> 5;

    __shared__ float st[NNODE * DOBS];     // obs tile, 4KB
    __shared__ int sord[64];
    __shared__ unsigned sbits[5][2];
    __shared__ unsigned bitmap[128];       // 4096 bits: key = u*64 + v
    __shared__ int warpsum[4];

    // --- load obs tile (vectorized) + zero bitmap ---
    const float4* src4 = (const float4*)(obs + (size_t)b * NNODE * DOBS);
    float4* st4 = (float4*)st;
#pragma unroll
    for (int i = t; i < NNODE * DOBS / 4; i += 128) st4[i] = src4[i];
    bitmap[t] = 0u;
    __syncthreads();

    // --- write x region for this batch: 64*18 = 1152 floats contiguous ---
    {
        float e0 = ego[0], e1 = ego[1], o0 = other[0], o1 = other[1];
        float* xout = out + (size_t)b * NNODE * XROW;
#pragma unroll
        for (int i = t; i < NNODE * XROW; i += 128) {
            int node = i / XROW;
            int d = i - node * XROW;
            float v;
            if (d < DOBS) v = st[node * DOBS + d];
            else if (d == DOBS) v = (node == 0) ? e0 : o0;
            else v = (node == 0) ? e1 : o1;
            xout[i] = v;
        }
    }

    // --- stable rank by x (ties by index) ---
    if (t < 64) {
        float xi = st[t * DOBS];
        int r = 0;
#pragma unroll
        for (int j = 0; j < 64; j++) {
            float xj = st[j * DOBS];
            r += (xj < xi) || (xj == xi && j < t);
        }
        sord[r] = t;
    }
    __syncthreads();

    bool mm[5];
    int node = 0;
    if (t < 64) {
        node = sord[t];               // node at sorted position t
        float ys = st[node * DOBS + 1];
        const float T1 = (float)(1.0 / 3.0);
        const float T2 = (float)(2.0 / 3.0);
        bool f0 = (ys <= T1) && (ys > 0.0f);
        bool f1 = (ys > T1) && (ys <= T2);
        bool f2 = (ys >= T2) && (ys < 1.0f);
        mm[0] = f0; mm[1] = f1; mm[2] = f2; mm[3] = f0 || f1; mm[4] = f1 || f2;
#pragma unroll
        for (int m = 0; m < 5; m++) {
            unsigned bal = __ballot_sync(0xffffffffu, mm[m]);
            if (lane == 0) sbits[m][w] = bal;
        }
    }
    __syncthreads();

    if (t < 64) {
#pragma unroll
        for (int m = 0; m < 5; m++) {
            if (mm[m] && t < 63) {
                unsigned long long bits =
                    ((unsigned long long)sbits[m][1] << 32) | (unsigned long long)sbits[m][0];
                unsigned long long rest = bits >> (t + 1);
                if (rest) {
                    int nk = t + 1 + (__ffsll((long long)rest) - 1);
                    int v = sord[nk];
                    int k1 = node * 64 + v;
                    int k2 = v * 64 + node;
                    atomicOr(&bitmap[k1 >> 5], 1u << (k1 & 31));
                    atomicOr(&bitmap[k2 >> 5], 1u << (k2 & 31));
                }
            }
        }
    }
    __syncthreads();

    // --- compact: each of 128 threads owns one 32-bit bitmap word ---
    unsigned wv = bitmap[t];
    int c = __popc(wv);

    int inc = c;
#pragma unroll
    for (int d = 1; d < 32; d <<= 1) {
        int nv = __shfl_up_sync(0xffffffffu, inc, d);
        if (lane >= d) inc += nv;
    }
    if (lane == 31) warpsum[w] = inc;
    __syncthreads();
    int wprefix = 0;
#pragma unroll
    for (int j = 0; j < 4; j++) wprefix += (j < w) ? warpsum[j] : 0;
    int excl = inc - c + wprefix;
    if (t == 0) g_cnt[b] = warpsum[0] + warpsum[1] + warpsum[2] + warpsum[3];

    unsigned short* kb = g_keys + (size_t)b * KEY_STRIDE;
    int pos = excl;
    int kbase = t * 32;
    while (wv) {
        int bit = __ffs(wv) - 1;
        wv &= (wv - 1);
        kb[pos++] = (unsigned short)(kbase + bit);
    }
}

// ---------------------------------------------------------------------------
// Kernel 2: exclusive scan of g_cnt[8192] -> g_off, + g_total
// ---------------------------------------------------------------------------
__global__ void __launch_bounds__(1024) scan_counts() {
    int t = threadIdx.x;
    int lane = t & 31, wid = t >> 5;
    __shared__ int wsum[32];

    int base = t * 8;
    int v[8];
    int s = 0;
#pragma unroll
    for (int i = 0; i < 8; i++) {
        v[i] = s;
        s += g_cnt[base + i];
    }
    int inc = s;
#pragma unroll
    for (int d = 1; d < 32; d <<= 1) {
        int nv = __shfl_up_sync(0xffffffffu, inc, d);
        if (lane >= d) inc += nv;
    }
    if (lane == 31) wsum[wid] = inc;
    __syncthreads();
    if (wid == 0) {
        int wv = wsum[lane];
        int winc = wv;
#pragma unroll
        for (int d = 1; d < 32; d <<= 1) {
            int nv = __shfl_up_sync(0xffffffffu, winc, d);
            if (lane >= d) winc += nv;
        }
        wsum[lane] = winc - wv;   // exclusive warp offsets
    }
    __syncthreads();
    int excl = inc - s + wsum[wid];
#pragma unroll
    for (int i = 0; i < 8; i++) g_off[base + i] = excl + v[i];
    if (t == 1023) g_total = excl + s;
}

// ---------------------------------------------------------------------------
// Kernel 3: scatter valid edges + fill this block's share of the -1 pad
// ---------------------------------------------------------------------------
__global__ void __launch_bounds__(128) scatter_pad(float* __restrict__ out) {
    int b = blockIdx.x;
    int t = threadIdx.x;
    int cnt = g_cnt[b];
    int off = g_off[b];
    const unsigned short* kb = g_keys + (size_t)b * KEY_STRIDE;
    float* src_out = out + XLEN;
    float* dst_out = out + XLEN + ETOT;
    int nb = b * NNODE;
    for (int i = t; i < cnt; i += 128) {
        int k = kb[i];
        src_out[off + i] = (float)(nb + (k >> 6));
        dst_out[off + i] = (float)(nb + (k & 63));
    }
    // pad share
    int T = g_total;
    int P = ETOT - T;
    int chunk = (P + B - 1) / B;
    int start = T + b * chunk;
    int end = start + chunk;
    if (end > ETOT) end = ETOT;
    for (int i = start + t; i < end; i += 128) {
        src_out[i] = -1.0f;
        dst_out[i] = -1.0f;
    }
}

// ---------------------------------------------------------------------------
extern "C" void kernel_launch(void* const* d_in, const int* in_sizes, int n_in,
                              void* d_out, int out_size) {
    const float* obs = (const float*)d_in[0];
    const float* ego = (const float*)d_in[1];
    const float* other = (const float*)d_in[2];
    float* out = (float*)d_out;

    build_edges_x<<<B, 128>>>(obs, ego, other, out);
    scan_counts<<<1, 1024>>>();
    scatter_pad<<<B, 128>>>(out);
}